// round 8
// baseline (speedup 1.0000x reference)
#include <cuda_runtime.h>
#include <cuda_bf16.h>
#include <math.h>
#include <stdint.h>

#define NSPK 512
#define UUT  32
#define DIM  512
#define MROW 16384          // 512*32
#define EPSF 1e-8f

// ------------------------- device scratch (no allocs) ------------------------
__device__ __nv_bfloat16 g_A[(size_t)MROW * DIM];   // 16 MB bf16(e), [row][dim]
__device__ __nv_bfloat16 g_B[(size_t)NSPK * DIM];   // 0.5 MB centroids, [speaker][dim]
__device__ float g_invA[MROW];
__device__ float g_se[MROW];                        // sum of exp per row
__device__ float g_vd[MROW];                        // diag value per row

// ------------------------------- PTX helpers ---------------------------------
__device__ __forceinline__ uint32_t smem_u32(const void* p) {
    uint32_t a;
    asm("{ .reg .u64 t; cvta.to.shared.u64 t, %1; cvt.u32.u64 %0, t; }"
        : "=r"(a) : "l"(p));
    return a;
}

#define CP_ASYNC16(dst, src) \
    asm volatile("cp.async.cg.shared.global [%0], [%1], 16;" :: "r"(dst), "l"(src))
#define CP_COMMIT() asm volatile("cp.async.commit_group;" ::: "memory")
#define CP_WAIT2()  asm volatile("cp.async.wait_group 2;" ::: "memory")
#define CP_WAIT1()  asm volatile("cp.async.wait_group 1;" ::: "memory")
#define CP_WAIT0()  asm volatile("cp.async.wait_group 0;" ::: "memory")

#define LDSM_X4(r, addr) \
    asm volatile("ldmatrix.sync.aligned.m8n8.x4.shared.b16 {%0,%1,%2,%3}, [%4];" \
        : "=r"((r)[0]), "=r"((r)[1]), "=r"((r)[2]), "=r"((r)[3]) : "r"(addr))

#define MMA16816(c, a, b0, b1) \
    asm volatile("mma.sync.aligned.m16n8k16.row.col.f32.bf16.bf16.f32 " \
        "{%0,%1,%2,%3}, {%4,%5,%6,%7}, {%8,%9}, {%0,%1,%2,%3};" \
        : "+f"((c)[0]), "+f"((c)[1]), "+f"((c)[2]), "+f"((c)[3]) \
        : "r"((a)[0]), "r"((a)[1]), "r"((a)[2]), "r"((a)[3]), "r"(b0), "r"(b1))

// Swizzled tile offset (128 rows x 32 bf16 = 64B/row, 2 rows per 128B line)
__device__ __forceinline__ uint32_t aoff(int row, int g) {
    int line = row >> 1;
    int gi = ((row & 1) << 2) | g;
    return (uint32_t)(line * 128 + ((gi ^ (line & 7)) << 4));
}

__device__ __forceinline__ uint32_t pack2(float x, float y) {
    __nv_bfloat162 p;
    p.x = __float2bfloat16(x);
    p.y = __float2bfloat16(y);
    return *reinterpret_cast<uint32_t*>(&p);
}

// -----------------------------------------------------------------------------
// Kernel 1 (prep): block = speaker (1024 thr, warp = utterance). Reads e ONCE.
//  - bf16 convert -> g_A (16B packed stores) + per-row inverse norms
//  - fp32 row data -> padded smem -> column sums -> normalized centroid -> g_B
//  - zeroes g_se and d_out
// smem: cp[32][516] fp32 (66048 B) + red[512] (2048 B)
// -----------------------------------------------------------------------------
#define PREP_SMEM (32 * 516 * 4 + 512 * 4)

__global__ __launch_bounds__(1024) void prep_kernel(const float* __restrict__ e,
                                                    float* __restrict__ out) {
    extern __shared__ float cp[];                // [32][516]
    float* red = cp + 32 * 516;                  // [512]

    int j = blockIdx.x, tid = threadIdx.x;
    int u = tid >> 5, lane = tid & 31;
    if (j == 0 && tid == 0) out[0] = 0.f;
    if (tid < 32) g_se[j * 32 + tid] = 0.f;

    int r = j * UUT + u;
    const float4* src = (const float4*)(e + (size_t)r * DIM);
    uint4* dst = (uint4*)(g_A + (size_t)r * DIM);

    // lane owns dims [8l..8l+7] and [256+8l..256+8l+7]
    float4 v0 = src[2 * lane];
    float4 v1 = src[2 * lane + 1];
    float4 v2 = src[2 * lane + 64];
    float4 v3 = src[2 * lane + 65];

    float ss = v0.x*v0.x + v0.y*v0.y + v0.z*v0.z + v0.w*v0.w
             + v1.x*v1.x + v1.y*v1.y + v1.z*v1.z + v1.w*v1.w
             + v2.x*v2.x + v2.y*v2.y + v2.z*v2.z + v2.w*v2.w
             + v3.x*v3.x + v3.y*v3.y + v3.z*v3.z + v3.w*v3.w;

    uint4 s0 = make_uint4(pack2(v0.x, v0.y), pack2(v0.z, v0.w),
                          pack2(v1.x, v1.y), pack2(v1.z, v1.w));
    uint4 s1 = make_uint4(pack2(v2.x, v2.y), pack2(v2.z, v2.w),
                          pack2(v3.x, v3.y), pack2(v3.z, v3.w));
    dst[lane]      = s0;
    dst[32 + lane] = s1;

    float4* cprow = (float4*)(cp + u * 516);
    cprow[2 * lane]      = v0;
    cprow[2 * lane + 1]  = v1;
    cprow[64 + 2 * lane] = v2;
    cprow[65 + 2 * lane] = v3;

#pragma unroll
    for (int s = 16; s > 0; s >>= 1) ss += __shfl_xor_sync(0xffffffffu, ss, s);
    if (lane == 0) g_invA[r] = 1.0f / fmaxf(sqrtf(ss), EPSF);

    __syncthreads();

    // column sums (centroid * 32); threads 0..511, one dim each
    float cs = 0.f;
    if (tid < 512) {
#pragma unroll
        for (int uu = 0; uu < 32; ++uu) cs += cp[uu * 516 + tid];
        red[tid] = cs * cs;
    }
    __syncthreads();
    for (int s = 256; s > 0; s >>= 1) {
        if (tid < s) red[tid] += red[tid + s];
        __syncthreads();
    }
    if (tid < 512) {
        float inv = 1.0f / fmaxf(sqrtf(red[0]), 32.f * EPSF);
        g_B[(size_t)j * DIM + tid] = __float2bfloat16(cs * inv);
    }
}

// -----------------------------------------------------------------------------
// Kernel 2: bf16 mma.sync GEMM (M=16384, N=512, K=512), BM=BN=128, BK=32,
// 3-stage cp.async pipeline, fused softmax-partial epilogue.
// B is [n][k] row-major (=B^T): B fragments via NON-trans ldmatrix, identical
// tile machinery to A.
// -----------------------------------------------------------------------------
#define NSTAGE_K 16   // DIM / 32

__global__ __launch_bounds__(256) void gemm_fused_kernel(const float* __restrict__ wp,
                                                         const float* __restrict__ bp) {
    __shared__ __align__(1024) char smem[49152];  // 3 stages x (A 8K + B 8K)

    int tid = threadIdx.x;
    int lane = tid & 31, wid = tid >> 5;
    int warp_m = wid & 1, warp_n = wid >> 1;       // 2 x 4 warps
    int nBase = blockIdx.x * 128, mBase = blockIdx.y * 128;

    uint32_t sbase = smem_u32(smem);

    int row0 = tid >> 2, g0 = tid & 3;             // shared slot mapping for A and B
    uint32_t offs0 = aoff(row0, g0), offs1 = aoff(row0 + 64, g0);
    const __nv_bfloat16* aptr0 = g_A + (size_t)(mBase + row0) * DIM + g0 * 8;
    const __nv_bfloat16* aptr1 = aptr0 + (size_t)64 * DIM;
    const __nv_bfloat16* bptr0 = g_B + (size_t)(nBase + row0) * DIM + g0 * 8;
    const __nv_bfloat16* bptr1 = bptr0 + (size_t)64 * DIM;

    float c[4][4][4];
#pragma unroll
    for (int i = 0; i < 4; ++i)
#pragma unroll
        for (int j = 0; j < 4; ++j)
#pragma unroll
            for (int q = 0; q < 4; ++q) c[i][j][q] = 0.f;

#define LOAD_STAGE(s, kt) do {                                                  \
        int k0 = (kt) * 32;                                                     \
        uint32_t sA_ = sbase + (s) * 16384;                                     \
        uint32_t sB_ = sA_ + 8192;                                              \
        CP_ASYNC16(sA_ + offs0, aptr0 + k0);                                    \
        CP_ASYNC16(sA_ + offs1, aptr1 + k0);                                    \
        CP_ASYNC16(sB_ + offs0, bptr0 + k0);                                    \
        CP_ASYNC16(sB_ + offs1, bptr1 + k0);                                    \
        CP_COMMIT();                                                            \
    } while (0)

    LOAD_STAGE(0, 0);
    LOAD_STAGE(1, 1);
    LOAD_STAGE(2, 2);

    int lrow = lane & 15, lsel = lane >> 4;

    for (int kt = 0; kt < NSTAGE_K; ++kt) {
        if (kt < NSTAGE_K - 2)      CP_WAIT2();
        else if (kt == NSTAGE_K - 2) CP_WAIT1();
        else                         CP_WAIT0();
        __syncthreads();

        int s = kt % 3;
        uint32_t sA = sbase + s * 16384;
        uint32_t sB = sA + 8192;

#pragma unroll
        for (int kh = 0; kh < 2; ++kh) {
            uint32_t a[4][4], bb[2][4];
#pragma unroll
            for (int mt = 0; mt < 4; ++mt) {
                int row = warp_m * 64 + mt * 16 + lrow;
                LDSM_X4(a[mt], sA + aoff(row, kh * 2 + lsel));
            }
#pragma unroll
            for (int nt = 0; nt < 2; ++nt) {
                int nrow = warp_n * 32 + nt * 16 + lrow;
                LDSM_X4(bb[nt], sB + aoff(nrow, kh * 2 + lsel));
            }
#pragma unroll
            for (int mt = 0; mt < 4; ++mt)
#pragma unroll
                for (int nt = 0; nt < 2; ++nt)
#pragma unroll
                    for (int t8 = 0; t8 < 2; ++t8)
                        MMA16816(c[mt][nt * 2 + t8], a[mt], bb[nt][t8], bb[nt][t8 + 2]);
        }
        __syncthreads();
        if (kt + 3 < NSTAGE_K) LOAD_STAGE((kt + 3) % 3, kt + 3);
    }
#undef LOAD_STAGE

    // ---------------- fused epilogue: partial sum-exp + diag -----------------
    float* se_sm = (float*)smem;    // stage memory is dead now
    __syncthreads();
    if (tid < 128) se_sm[tid] = 0.f;
    __syncthreads();

    float wv = *wp, bv = *bp;
#pragma unroll
    for (int mt = 0; mt < 4; ++mt) {
#pragma unroll
        for (int sr = 0; sr < 2; ++sr) {
            int row_l = warp_m * 64 + mt * 16 + (lane >> 2) + sr * 8;
            int row_g = mBase + row_l;
            float sc = wv * g_invA[row_g];
            int jdiag = row_g >> 5;
            float part = 0.f;
#pragma unroll
            for (int nt = 0; nt < 2; ++nt)
#pragma unroll
                for (int t8 = 0; t8 < 2; ++t8)
#pragma unroll
                    for (int cc = 0; cc < 2; ++cc) {
                        int col_g = nBase + warp_n * 32 + nt * 16 + t8 * 8
                                  + (lane & 3) * 2 + cc;
                        float v = fmaf(c[mt][nt * 2 + t8][sr * 2 + cc], sc, bv);
                        part += __expf(v);
                        if (col_g == jdiag) g_vd[row_g] = v;
                    }
            part += __shfl_xor_sync(0xffffffffu, part, 1);
            part += __shfl_xor_sync(0xffffffffu, part, 2);
            if ((lane & 3) == 0) atomicAdd(&se_sm[row_l], part);
        }
    }
    __syncthreads();
    if (tid < 128) atomicAdd(&g_se[mBase + tid], se_sm[tid]);
}

// -----------------------------------------------------------------------------
// Kernel 3: loss = mean(log(se) - vd)
// -----------------------------------------------------------------------------
__global__ __launch_bounds__(256) void final_kernel(float* __restrict__ out) {
    int idx = blockIdx.x * 256 + threadIdx.x;
    float v = __logf(g_se[idx]) - g_vd[idx];
#pragma unroll
    for (int s = 16; s > 0; s >>= 1) v += __shfl_xor_sync(0xffffffffu, v, s);
    __shared__ float part[8];
    int wid = threadIdx.x >> 5, lane = threadIdx.x & 31;
    if (lane == 0) part[wid] = v;
    __syncthreads();
    if (threadIdx.x == 0) {
        float s = 0.f;
#pragma unroll
        for (int i = 0; i < 8; ++i) s += part[i];
        atomicAdd(out, s * (1.0f / (float)MROW));
    }
}

// -----------------------------------------------------------------------------
extern "C" void kernel_launch(void* const* d_in, const int* in_sizes, int n_in,
                              void* d_out, int out_size) {
    const float* e = (const float*)d_in[0];  // (512, 32, 512) fp32
    const float* w = (const float*)d_in[1];
    const float* b = (const float*)d_in[2];
    float* out = (float*)d_out;

    cudaFuncSetAttribute(prep_kernel,
                         cudaFuncAttributeMaxDynamicSharedMemorySize, PREP_SMEM);

    prep_kernel<<<NSPK, 1024, PREP_SMEM>>>(e, out);
    gemm_fused_kernel<<<dim3(NSPK / 128, MROW / 128), 256>>>(w, b);
    final_kernel<<<MROW / 256, 256>>>(out);
}

// round 9
// speedup vs baseline: 1.5915x; 1.5915x over previous
#include <cuda_runtime.h>
#include <cuda_bf16.h>
#include <math.h>
#include <stdint.h>

#define NSPK 512
#define UUT  32
#define DIM  512
#define MROW 16384          // 512*32
#define EPSF 1e-8f

// ------------------------- device scratch (no allocs) ------------------------
__device__ __nv_bfloat16 g_A[(size_t)MROW * DIM];   // 16 MB bf16(e)
__device__ __nv_bfloat16 g_B[(size_t)DIM * NSPK];   // 512x512 normalized centroids [k][n]
__device__ float g_invA[MROW];
__device__ float g_se[MROW];                        // sum of exp per row
__device__ float g_vd[MROW];                        // diag value per row

// ------------------------------- PTX helpers ---------------------------------
__device__ __forceinline__ uint32_t smem_u32(const void* p) {
    uint32_t a;
    asm("{ .reg .u64 t; cvta.to.shared.u64 t, %1; cvt.u32.u64 %0, t; }"
        : "=r"(a) : "l"(p));
    return a;
}

#define CP_ASYNC16(dst, src) \
    asm volatile("cp.async.cg.shared.global [%0], [%1], 16;" :: "r"(dst), "l"(src))
#define CP_COMMIT() asm volatile("cp.async.commit_group;" ::: "memory")
#define CP_WAIT1()  asm volatile("cp.async.wait_group 1;" ::: "memory")
#define CP_WAIT0()  asm volatile("cp.async.wait_group 0;" ::: "memory")

#define LDSM_X4(r, addr) \
    asm volatile("ldmatrix.sync.aligned.m8n8.x4.shared.b16 {%0,%1,%2,%3}, [%4];" \
        : "=r"((r)[0]), "=r"((r)[1]), "=r"((r)[2]), "=r"((r)[3]) : "r"(addr))
#define LDSM_X4T(r, addr) \
    asm volatile("ldmatrix.sync.aligned.m8n8.x4.trans.shared.b16 {%0,%1,%2,%3}, [%4];" \
        : "=r"((r)[0]), "=r"((r)[1]), "=r"((r)[2]), "=r"((r)[3]) : "r"(addr))

#define MMA16816(c, a, b0, b1) \
    asm volatile("mma.sync.aligned.m16n8k16.row.col.f32.bf16.bf16.f32 " \
        "{%0,%1,%2,%3}, {%4,%5,%6,%7}, {%8,%9}, {%0,%1,%2,%3};" \
        : "+f"((c)[0]), "+f"((c)[1]), "+f"((c)[2]), "+f"((c)[3]) \
        : "r"((a)[0]), "r"((a)[1]), "r"((a)[2]), "r"((a)[3]), "r"(b0), "r"(b1))

// Swizzled smem offsets (validated R5/R6 scheme)
__device__ __forceinline__ uint32_t aoff(int row, int g) {
    int line = row >> 1;
    int gi = ((row & 1) << 2) | g;
    return (uint32_t)(line * 128 + ((gi ^ (line & 7)) << 4));
}
__device__ __forceinline__ uint32_t boff(int k, int g) {
    return (uint32_t)(k * 256 + ((g ^ (k & 7)) << 4));
}

// -----------------------------------------------------------------------------
// Kernel 1 (prep): block = speaker, 512 threads (16 warps x 2 rows each).
//  - bf16-convert rows into g_A + per-row inv norms
//  - centroid sum -> normalize -> bf16 into g_B [k][n]
//  - zeroes g_se rows and d_out
// -----------------------------------------------------------------------------
__global__ __launch_bounds__(512) void prep_kernel(const float* __restrict__ e,
                                                   float* __restrict__ out) {
    int j = blockIdx.x, tid = threadIdx.x;
    int w = tid >> 5, lane = tid & 31;
    if (j == 0 && tid == 0) out[0] = 0.f;
    if (tid < 32) g_se[j * 32 + tid] = 0.f;

    __shared__ float cpart[16][512];   // per-warp centroid partials (32 KB)
    __shared__ float red[512];

    float acc[16];
#pragma unroll
    for (int i = 0; i < 16; ++i) acc[i] = 0.f;

#pragma unroll
    for (int uu = 0; uu < 2; ++uu) {
        int u = w * 2 + uu;
        int r = j * UUT + u;
        const float4* src = (const float4*)(e + (size_t)r * DIM);
        __nv_bfloat162* dst = (__nv_bfloat162*)(g_A + (size_t)r * DIM);
        float ss = 0.f;
#pragma unroll
        for (int i = 0; i < 4; ++i) {
            float4 v = src[i * 32 + lane];
            ss += v.x * v.x + v.y * v.y + v.z * v.z + v.w * v.w;
            acc[i * 4 + 0] += v.x; acc[i * 4 + 1] += v.y;
            acc[i * 4 + 2] += v.z; acc[i * 4 + 3] += v.w;
            __nv_bfloat162 p0, p1;
            p0.x = __float2bfloat16(v.x); p0.y = __float2bfloat16(v.y);
            p1.x = __float2bfloat16(v.z); p1.y = __float2bfloat16(v.w);
            dst[(i * 32 + lane) * 2]     = p0;
            dst[(i * 32 + lane) * 2 + 1] = p1;
        }
#pragma unroll
        for (int s = 16; s > 0; s >>= 1) ss += __shfl_xor_sync(0xffffffffu, ss, s);
        if (lane == 0) g_invA[r] = 1.0f / fmaxf(sqrtf(ss), EPSF);
    }

#pragma unroll
    for (int i = 0; i < 4; ++i) {
        int d = (i * 32 + lane) * 4;
        cpart[w][d + 0] = acc[i * 4 + 0];
        cpart[w][d + 1] = acc[i * 4 + 1];
        cpart[w][d + 2] = acc[i * 4 + 2];
        cpart[w][d + 3] = acc[i * 4 + 3];
    }
    __syncthreads();

    // all 512 threads: one dim each
    float cs = 0.f;
#pragma unroll
    for (int p = 0; p < 16; ++p) cs += cpart[p][tid];
    red[tid] = cs * cs;
    __syncthreads();
    for (int s = 256; s > 0; s >>= 1) {
        if (tid < s) red[tid] += red[tid + s];
        __syncthreads();
    }
    float inv = 1.0f / fmaxf(sqrtf(red[0]), 32.f * EPSF);
    g_B[(size_t)tid * NSPK + j] = __float2bfloat16(cs * inv);
}

// -----------------------------------------------------------------------------
// Kernel 2: bf16 mma.sync GEMM (K=512) with FUSED softmax-partial epilogue.
// BM=128 BN=128 BK=32, 256 thr, cp.async double buffer.  (R6, unchanged)
// -----------------------------------------------------------------------------
#define NSTAGE_K 16   // DIM / 32

__global__ __launch_bounds__(256) void gemm_fused_kernel(const float* __restrict__ wp,
                                                         const float* __restrict__ bp) {
    __shared__ __align__(1024) char smem[32768];
    __shared__ float se_sm[128];

    int tid = threadIdx.x;
    int lane = tid & 31, wid = tid >> 5;
    int warp_m = wid & 1, warp_n = wid >> 1;
    int mBase = blockIdx.y * 128, nBase = blockIdx.x * 128;

    uint32_t sbase = smem_u32(smem);

    int arow0 = tid >> 2, ag = tid & 3;
    uint32_t aoffs0 = aoff(arow0, ag), aoffs1 = aoff(arow0 + 64, ag);
    const __nv_bfloat16* aptr0 = g_A + (size_t)(mBase + arow0) * DIM + ag * 8;
    const __nv_bfloat16* aptr1 = aptr0 + (size_t)64 * DIM;

    int brow0 = tid >> 4, bg = tid & 15;
    uint32_t boffs0 = boff(brow0, bg), boffs1 = boff(brow0 + 16, bg);
    const __nv_bfloat16* bptr0 = g_B + (size_t)brow0 * NSPK + nBase + bg * 8;
    const __nv_bfloat16* bptr1 = bptr0 + (size_t)16 * NSPK;

    if (tid < 128) se_sm[tid] = 0.f;

    float c[4][4][4];
#pragma unroll
    for (int i = 0; i < 4; ++i)
#pragma unroll
        for (int j = 0; j < 4; ++j)
#pragma unroll
            for (int q = 0; q < 4; ++q) c[i][j][q] = 0.f;

#define LOAD_STAGE(s, kt) do {                                                  \
        int k0 = (kt) * 32;                                                     \
        uint32_t sA_ = sbase + (s) * 8192;                                      \
        uint32_t sB_ = sbase + 16384 + (s) * 8192;                              \
        CP_ASYNC16(sA_ + aoffs0, aptr0 + k0);                                   \
        CP_ASYNC16(sA_ + aoffs1, aptr1 + k0);                                   \
        CP_ASYNC16(sB_ + boffs0, bptr0 + (size_t)k0 * NSPK);                    \
        CP_ASYNC16(sB_ + boffs1, bptr1 + (size_t)k0 * NSPK);                    \
        CP_COMMIT();                                                            \
    } while (0)

    LOAD_STAGE(0, 0);
    LOAD_STAGE(1, 1);

    int lrow = lane & 15, lsel = lane >> 4;

    for (int kt = 0; kt < NSTAGE_K; ++kt) {
        if (kt < NSTAGE_K - 1) CP_WAIT1(); else CP_WAIT0();
        __syncthreads();

        int s = kt & 1;
        uint32_t sA = sbase + s * 8192;
        uint32_t sB = sbase + 16384 + s * 8192;

#pragma unroll
        for (int kh = 0; kh < 2; ++kh) {
            uint32_t a[4][4], b[2][4];
#pragma unroll
            for (int mt = 0; mt < 4; ++mt) {
                int row = warp_m * 64 + mt * 16 + lrow;
                LDSM_X4(a[mt], sA + aoff(row, kh * 2 + lsel));
            }
#pragma unroll
            for (int nt = 0; nt < 2; ++nt) {
                int k = kh * 16 + lrow;
                LDSM_X4T(b[nt], sB + boff(k, warp_n * 4 + nt * 2 + lsel));
            }
#pragma unroll
            for (int mt = 0; mt < 4; ++mt)
#pragma unroll
                for (int n8 = 0; n8 < 4; ++n8) {
                    uint32_t b0 = b[n8 >> 1][(n8 & 1) * 2];
                    uint32_t b1 = b[n8 >> 1][(n8 & 1) * 2 + 1];
                    MMA16816(c[mt][n8], a[mt], b0, b1);
                }
        }
        __syncthreads();
        if (kt + 2 < NSTAGE_K) LOAD_STAGE(kt & 1, kt + 2);
    }
#undef LOAD_STAGE

    // ---------------- fused epilogue: partial sum-exp + diag -----------------
    float wv = *wp, bv = *bp;
#pragma unroll
    for (int mt = 0; mt < 4; ++mt) {
#pragma unroll
        for (int sr = 0; sr < 2; ++sr) {
            int row_l = warp_m * 64 + mt * 16 + (lane >> 2) + sr * 8;
            int row_g = mBase + row_l;
            float sc = wv * g_invA[row_g];
            int jdiag = row_g >> 5;
            float part = 0.f;
#pragma unroll
            for (int n8 = 0; n8 < 4; ++n8) {
#pragma unroll
                for (int cc = 0; cc < 2; ++cc) {
                    int col_g = nBase + warp_n * 32 + n8 * 8 + (lane & 3) * 2 + cc;
                    float v = fmaf(c[mt][n8][sr * 2 + cc], sc, bv);
                    part += __expf(v);
                    if (col_g == jdiag) g_vd[row_g] = v;
                }
            }
            part += __shfl_xor_sync(0xffffffffu, part, 1);
            part += __shfl_xor_sync(0xffffffffu, part, 2);
            if ((lane & 3) == 0) atomicAdd(&se_sm[row_l], part);
        }
    }
    __syncthreads();
    if (tid < 128) atomicAdd(&g_se[mBase + tid], se_sm[tid]);
}

// -----------------------------------------------------------------------------
// Kernel 3: loss = mean(log(se) - vd)
// -----------------------------------------------------------------------------
__global__ __launch_bounds__(256) void final_kernel(float* __restrict__ out) {
    int idx = blockIdx.x * 256 + threadIdx.x;
    float v = __logf(g_se[idx]) - g_vd[idx];
#pragma unroll
    for (int s = 16; s > 0; s >>= 1) v += __shfl_xor_sync(0xffffffffu, v, s);
    __shared__ float part[8];
    int wid = threadIdx.x >> 5, lane = threadIdx.x & 31;
    if (lane == 0) part[wid] = v;
    __syncthreads();
    if (threadIdx.x == 0) {
        float s = 0.f;
#pragma unroll
        for (int i = 0; i < 8; ++i) s += part[i];
        atomicAdd(out, s * (1.0f / (float)MROW));
    }
}

// -----------------------------------------------------------------------------
extern "C" void kernel_launch(void* const* d_in, const int* in_sizes, int n_in,
                              void* d_out, int out_size) {
    const float* e = (const float*)d_in[0];  // (512, 32, 512) fp32
    const float* w = (const float*)d_in[1];
    const float* b = (const float*)d_in[2];
    float* out = (float*)d_out;

    prep_kernel<<<NSPK, 512>>>(e, out);
    gemm_fused_kernel<<<dim3(NSPK / 128, MROW / 128), 256>>>(w, b);
    final_kernel<<<MROW / 256, 256>>>(out);
}

// round 10
// speedup vs baseline: 1.7913x; 1.1255x over previous
#include <cuda_runtime.h>
#include <cuda_bf16.h>
#include <math.h>
#include <stdint.h>

#define NSPK 512
#define UUT  32
#define DIM  512
#define MROW 16384          // 512*32
#define EPSF 1e-8f

// ------------------------- device scratch (no allocs) ------------------------
__device__ __nv_bfloat16 g_A[(size_t)MROW * DIM];   // 16 MB bf16(e)
__device__ __nv_bfloat16 g_B[(size_t)DIM * NSPK];   // 512x512 normalized centroids [k][n]
__device__ float g_invA[MROW];
__device__ float g_se[MROW];                        // sum of exp per row
__device__ float g_vd[MROW];                        // diag value per row

// ------------------------------- PTX helpers ---------------------------------
__device__ __forceinline__ uint32_t smem_u32(const void* p) {
    uint32_t a;
    asm("{ .reg .u64 t; cvta.to.shared.u64 t, %1; cvt.u32.u64 %0, t; }"
        : "=r"(a) : "l"(p));
    return a;
}

#define CP_ASYNC16(dst, src) \
    asm volatile("cp.async.cg.shared.global [%0], [%1], 16;" :: "r"(dst), "l"(src))
#define CP_COMMIT() asm volatile("cp.async.commit_group;" ::: "memory")
#define CP_WAIT1()  asm volatile("cp.async.wait_group 1;" ::: "memory")
#define CP_WAIT0()  asm volatile("cp.async.wait_group 0;" ::: "memory")

#define LDSM_X4(r, addr) \
    asm volatile("ldmatrix.sync.aligned.m8n8.x4.shared.b16 {%0,%1,%2,%3}, [%4];" \
        : "=r"((r)[0]), "=r"((r)[1]), "=r"((r)[2]), "=r"((r)[3]) : "r"(addr))
#define LDSM_X4T(r, addr) \
    asm volatile("ldmatrix.sync.aligned.m8n8.x4.trans.shared.b16 {%0,%1,%2,%3}, [%4];" \
        : "=r"((r)[0]), "=r"((r)[1]), "=r"((r)[2]), "=r"((r)[3]) : "r"(addr))

#define MMA16816(c, a, b0, b1) \
    asm volatile("mma.sync.aligned.m16n8k16.row.col.f32.bf16.bf16.f32 " \
        "{%0,%1,%2,%3}, {%4,%5,%6,%7}, {%8,%9}, {%0,%1,%2,%3};" \
        : "+f"((c)[0]), "+f"((c)[1]), "+f"((c)[2]), "+f"((c)[3]) \
        : "r"((a)[0]), "r"((a)[1]), "r"((a)[2]), "r"((a)[3]), "r"(b0), "r"(b1))

// A tile: 128 rows x 128B (64 bf16/row), classic SW128 swizzle, g = granule 0..7
__device__ __forceinline__ uint32_t aoff2(int row, int g) {
    return (uint32_t)(row * 128 + ((g ^ (row & 7)) << 4));
}
// B tile: 64 rows (k) x 256B (128 bf16), 16 granules/row, XOR with k&7 (R6-proven)
__device__ __forceinline__ uint32_t boff(int k, int g) {
    return (uint32_t)(k * 256 + ((g ^ (k & 7)) << 4));
}

// -----------------------------------------------------------------------------
// Kernel 1 (prep): block = speaker, 512 threads (16 warps x 2 rows each).
// Both rows' loads batched up front for MLP=8.
// -----------------------------------------------------------------------------
__global__ __launch_bounds__(512) void prep_kernel(const float* __restrict__ e,
                                                   float* __restrict__ out) {
    int j = blockIdx.x, tid = threadIdx.x;
    int w = tid >> 5, lane = tid & 31;
    if (j == 0 && tid == 0) out[0] = 0.f;
    if (tid < 32) g_se[j * 32 + tid] = 0.f;

    __shared__ float cpart[16][512];   // per-warp centroid partials (32 KB)
    __shared__ float red[512];

    int r0 = j * UUT + w * 2;
    const float4* src0 = (const float4*)(e + (size_t)r0 * DIM);
    const float4* src1 = (const float4*)(e + (size_t)(r0 + 1) * DIM);

    // batch all 8 independent loads first (MLP 8)
    float4 v[2][4];
#pragma unroll
    for (int i = 0; i < 4; ++i) v[0][i] = src0[i * 32 + lane];
#pragma unroll
    for (int i = 0; i < 4; ++i) v[1][i] = src1[i * 32 + lane];

    float acc[16];
#pragma unroll
    for (int i = 0; i < 16; ++i)
        acc[i] = v[0][0].x;  // placeholder overwritten below

#pragma unroll
    for (int i = 0; i < 4; ++i) {
        acc[i * 4 + 0] = v[0][i].x + v[1][i].x;
        acc[i * 4 + 1] = v[0][i].y + v[1][i].y;
        acc[i * 4 + 2] = v[0][i].z + v[1][i].z;
        acc[i * 4 + 3] = v[0][i].w + v[1][i].w;
    }

#pragma unroll
    for (int uu = 0; uu < 2; ++uu) {
        int r = r0 + uu;
        __nv_bfloat162* dst = (__nv_bfloat162*)(g_A + (size_t)r * DIM);
        float ss = 0.f;
#pragma unroll
        for (int i = 0; i < 4; ++i) {
            float4 q = v[uu][i];
            ss += q.x * q.x + q.y * q.y + q.z * q.z + q.w * q.w;
            __nv_bfloat162 p0, p1;
            p0.x = __float2bfloat16(q.x); p0.y = __float2bfloat16(q.y);
            p1.x = __float2bfloat16(q.z); p1.y = __float2bfloat16(q.w);
            dst[(i * 32 + lane) * 2]     = p0;
            dst[(i * 32 + lane) * 2 + 1] = p1;
        }
#pragma unroll
        for (int s = 16; s > 0; s >>= 1) ss += __shfl_xor_sync(0xffffffffu, ss, s);
        if (lane == 0) g_invA[r] = 1.0f / fmaxf(sqrtf(ss), EPSF);
    }

#pragma unroll
    for (int i = 0; i < 4; ++i) {
        int d = (i * 32 + lane) * 4;
        cpart[w][d + 0] = acc[i * 4 + 0];
        cpart[w][d + 1] = acc[i * 4 + 1];
        cpart[w][d + 2] = acc[i * 4 + 2];
        cpart[w][d + 3] = acc[i * 4 + 3];
    }
    __syncthreads();

    float cs = 0.f;
#pragma unroll
    for (int p = 0; p < 16; ++p) cs += cpart[p][tid];
    red[tid] = cs * cs;
    __syncthreads();
    for (int s = 256; s > 0; s >>= 1) {
        if (tid < s) red[tid] += red[tid + s];
        __syncthreads();
    }
    float inv = 1.0f / fmaxf(sqrtf(red[0]), 32.f * EPSF);
    g_B[(size_t)tid * NSPK + j] = __float2bfloat16(cs * inv);
}

// -----------------------------------------------------------------------------
// Kernel 2: bf16 mma.sync GEMM, BM=BN=128, BK=64, 2-stage cp.async,
// fused softmax-partial epilogue.  8 K-tiles -> half the barriers of R6.
// smem: 2 stages x (A 16KB + B 16KB) = 64KB dynamic + 512B se_sm.
// -----------------------------------------------------------------------------
#define NKT 8            // DIM / 64
#define GEMM_SMEM (65536 + 512)

__global__ __launch_bounds__(256) void gemm_fused_kernel(const float* __restrict__ wp,
                                                         const float* __restrict__ bp) {
    extern __shared__ __align__(1024) char smem[];
    float* se_sm = (float*)(smem + 65536);

    int tid = threadIdx.x;
    int lane = tid & 31, wid = tid >> 5;
    int warp_m = wid & 1, warp_n = wid >> 1;
    int mBase = blockIdx.y * 128, nBase = blockIdx.x * 128;

    uint32_t sbase = smem_u32(smem);

    // cp.async slots: A 32 rows/pass x 8 granules; B 16 rows/pass x 16 granules
    int arow = tid >> 3, ag = tid & 7;
    int brow = tid >> 4, bg = tid & 15;
    const __nv_bfloat16* aptr = g_A + (size_t)(mBase + arow) * DIM + ag * 8;
    const __nv_bfloat16* bptr = g_B + (size_t)brow * NSPK + nBase + bg * 8;

    float c[4][4][4];
#pragma unroll
    for (int i = 0; i < 4; ++i)
#pragma unroll
        for (int j = 0; j < 4; ++j)
#pragma unroll
            for (int q = 0; q < 4; ++q) c[i][j][q] = 0.f;

#define LOAD_STAGE(s, kt) do {                                                  \
        int k0 = (kt) * 64;                                                     \
        uint32_t sA_ = sbase + (s) * 32768;                                     \
        uint32_t sB_ = sA_ + 16384;                                             \
        CP_ASYNC16(sA_ + aoff2(arow,      ag), aptr + k0);                      \
        CP_ASYNC16(sA_ + aoff2(arow + 32, ag), aptr + k0 + (size_t)32 * DIM);   \
        CP_ASYNC16(sA_ + aoff2(arow + 64, ag), aptr + k0 + (size_t)64 * DIM);   \
        CP_ASYNC16(sA_ + aoff2(arow + 96, ag), aptr + k0 + (size_t)96 * DIM);   \
        CP_ASYNC16(sB_ + boff(brow,      bg), bptr + (size_t)(k0     ) * NSPK); \
        CP_ASYNC16(sB_ + boff(brow + 16, bg), bptr + (size_t)(k0 + 16) * NSPK); \
        CP_ASYNC16(sB_ + boff(brow + 32, bg), bptr + (size_t)(k0 + 32) * NSPK); \
        CP_ASYNC16(sB_ + boff(brow + 48, bg), bptr + (size_t)(k0 + 48) * NSPK); \
        CP_COMMIT();                                                            \
    } while (0)

    LOAD_STAGE(0, 0);
    LOAD_STAGE(1, 1);

    int lrow = lane & 15, lsel = lane >> 4;

    for (int kt = 0; kt < NKT; ++kt) {
        if (kt < NKT - 1) CP_WAIT1(); else CP_WAIT0();
        __syncthreads();

        int s = kt & 1;
        uint32_t sA = sbase + s * 32768;
        uint32_t sB = sA + 16384;

#pragma unroll
        for (int kh = 0; kh < 4; ++kh) {
            uint32_t a[4][4], b[2][4];
#pragma unroll
            for (int mt = 0; mt < 4; ++mt) {
                int row = warp_m * 64 + mt * 16 + lrow;
                LDSM_X4(a[mt], sA + aoff2(row, kh * 2 + lsel));
            }
#pragma unroll
            for (int nt = 0; nt < 2; ++nt) {
                int k = kh * 16 + lrow;
                LDSM_X4T(b[nt], sB + boff(k, warp_n * 4 + nt * 2 + lsel));
            }
#pragma unroll
            for (int mt = 0; mt < 4; ++mt)
#pragma unroll
                for (int n8 = 0; n8 < 4; ++n8) {
                    uint32_t b0 = b[n8 >> 1][(n8 & 1) * 2];
                    uint32_t b1 = b[n8 >> 1][(n8 & 1) * 2 + 1];
                    MMA16816(c[mt][n8], a[mt], b0, b1);
                }
        }
        __syncthreads();
        if (kt + 2 < NKT) LOAD_STAGE(kt & 1, kt + 2);
    }
#undef LOAD_STAGE

    // ---------------- fused epilogue: partial sum-exp + diag -----------------
    if (tid < 128) se_sm[tid] = 0.f;
    __syncthreads();

    float wv = *wp, bv = *bp;
#pragma unroll
    for (int mt = 0; mt < 4; ++mt) {
#pragma unroll
        for (int sr = 0; sr < 2; ++sr) {
            int row_l = warp_m * 64 + mt * 16 + (lane >> 2) + sr * 8;
            int row_g = mBase + row_l;
            float sc = wv * g_invA[row_g];
            int jdiag = row_g >> 5;
            float part = 0.f;
#pragma unroll
            for (int n8 = 0; n8 < 4; ++n8) {
#pragma unroll
                for (int cc = 0; cc < 2; ++cc) {
                    int col_g = nBase + warp_n * 32 + n8 * 8 + (lane & 3) * 2 + cc;
                    float v = fmaf(c[mt][n8][sr * 2 + cc], sc, bv);
                    part += __expf(v);
                    if (col_g == jdiag) g_vd[row_g] = v;
                }
            }
            part += __shfl_xor_sync(0xffffffffu, part, 1);
            part += __shfl_xor_sync(0xffffffffu, part, 2);
            if ((lane & 3) == 0) atomicAdd(&se_sm[row_l], part);
        }
    }
    __syncthreads();
    if (tid < 128) atomicAdd(&g_se[mBase + tid], se_sm[tid]);
}

// -----------------------------------------------------------------------------
// Kernel 3: loss = mean(log(se) - vd)
// -----------------------------------------------------------------------------
__global__ __launch_bounds__(256) void final_kernel(float* __restrict__ out) {
    int idx = blockIdx.x * 256 + threadIdx.x;
    float v = __logf(g_se[idx]) - g_vd[idx];
#pragma unroll
    for (int s = 16; s > 0; s >>= 1) v += __shfl_xor_sync(0xffffffffu, v, s);
    __shared__ float part[8];
    int wid = threadIdx.x >> 5, lane = threadIdx.x & 31;
    if (lane == 0) part[wid] = v;
    __syncthreads();
    if (threadIdx.x == 0) {
        float s = 0.f;
#pragma unroll
        for (int i = 0; i < 8; ++i) s += part[i];
        atomicAdd(out, s * (1.0f / (float)MROW));
    }
}

// -----------------------------------------------------------------------------
extern "C" void kernel_launch(void* const* d_in, const int* in_sizes, int n_in,
                              void* d_out, int out_size) {
    const float* e = (const float*)d_in[0];  // (512, 32, 512) fp32
    const float* w = (const float*)d_in[1];
    const float* b = (const float*)d_in[2];
    float* out = (float*)d_out;

    cudaFuncSetAttribute(gemm_fused_kernel,
                         cudaFuncAttributeMaxDynamicSharedMemorySize, GEMM_SMEM);

    prep_kernel<<<NSPK, 512>>>(e, out);
    gemm_fused_kernel<<<dim3(NSPK / 128, MROW / 128), 256, GEMM_SMEM>>>(w, b);
    final_kernel<<<MROW / 256, 256>>>(out);
}

// round 11
// speedup vs baseline: 1.8038x; 1.0070x over previous
#include <cuda_runtime.h>
#include <cuda_bf16.h>
#include <math.h>
#include <stdint.h>

#define NSPK 512
#define UUT  32
#define DIM  512
#define MROW 16384          // 512*32
#define EPSF 1e-8f

// ------------------------- device scratch (no allocs) ------------------------
__device__ __nv_bfloat16 g_A[(size_t)MROW * DIM];   // 16 MB bf16(e)
__device__ __nv_bfloat16 g_B[(size_t)DIM * NSPK];   // 512x512 normalized centroids [k][n]
__device__ float g_invA[MROW];
__device__ float g_se[MROW];                        // sum of exp per row
__device__ float g_vd[MROW];                        // diag value per row

// ------------------------------- PTX helpers ---------------------------------
__device__ __forceinline__ uint32_t smem_u32(const void* p) {
    uint32_t a;
    asm("{ .reg .u64 t; cvta.to.shared.u64 t, %1; cvt.u32.u64 %0, t; }"
        : "=r"(a) : "l"(p));
    return a;
}

#define CP_ASYNC16(dst, src) \
    asm volatile("cp.async.cg.shared.global [%0], [%1], 16;" :: "r"(dst), "l"(src))
#define CP_COMMIT() asm volatile("cp.async.commit_group;" ::: "memory")
#define CP_WAIT2()  asm volatile("cp.async.wait_group 2;" ::: "memory")
#define CP_WAIT1()  asm volatile("cp.async.wait_group 1;" ::: "memory")
#define CP_WAIT0()  asm volatile("cp.async.wait_group 0;" ::: "memory")

#define LDSM_X4(r, addr) \
    asm volatile("ldmatrix.sync.aligned.m8n8.x4.shared.b16 {%0,%1,%2,%3}, [%4];" \
        : "=r"((r)[0]), "=r"((r)[1]), "=r"((r)[2]), "=r"((r)[3]) : "r"(addr))
#define LDSM_X4T(r, addr) \
    asm volatile("ldmatrix.sync.aligned.m8n8.x4.trans.shared.b16 {%0,%1,%2,%3}, [%4];" \
        : "=r"((r)[0]), "=r"((r)[1]), "=r"((r)[2]), "=r"((r)[3]) : "r"(addr))

#define MMA16816(c, a, b0, b1) \
    asm volatile("mma.sync.aligned.m16n8k16.row.col.f32.bf16.bf16.f32 " \
        "{%0,%1,%2,%3}, {%4,%5,%6,%7}, {%8,%9}, {%0,%1,%2,%3};" \
        : "+f"((c)[0]), "+f"((c)[1]), "+f"((c)[2]), "+f"((c)[3]) \
        : "r"((a)[0]), "r"((a)[1]), "r"((a)[2]), "r"((a)[3]), "r"(b0), "r"(b1))

// A tile: 128 rows x 128B (64 bf16/row), SW128 swizzle, g = granule 0..7
__device__ __forceinline__ uint32_t aoff2(int row, int g) {
    return (uint32_t)(row * 128 + ((g ^ (row & 7)) << 4));
}
// B tile: 64 rows (k) x 256B (128 bf16), 16 granules/row, XOR with k&7
__device__ __forceinline__ uint32_t boff(int k, int g) {
    return (uint32_t)(k * 256 + ((g ^ (k & 7)) << 4));
}

__device__ __forceinline__ uint32_t pack2(float x, float y) {
    __nv_bfloat162 p;
    p.x = __float2bfloat16(x);
    p.y = __float2bfloat16(y);
    return *reinterpret_cast<uint32_t*>(&p);
}

// -----------------------------------------------------------------------------
// Kernel 1a (conv): pure stream. warp = row; 4x LDG.128 -> 4x STG.64 + norm.
// No smem, no barriers. Also zeroes g_se and d_out.
// -----------------------------------------------------------------------------
__global__ __launch_bounds__(256) void conv_kernel(const float* __restrict__ e,
                                                   float* __restrict__ out) {
    int w = threadIdx.x >> 5, lane = threadIdx.x & 31;
    int r = blockIdx.x * 8 + w;
    if (blockIdx.x == 0 && threadIdx.x == 0) out[0] = 0.f;
    if (lane == 1) g_se[r] = 0.f;

    const float4* src = (const float4*)(e + (size_t)r * DIM);
    float4 v[4];
#pragma unroll
    for (int i = 0; i < 4; ++i) v[i] = src[i * 32 + lane];

    uint2* dst = (uint2*)(g_A + (size_t)r * DIM);
    float ss = 0.f;
#pragma unroll
    for (int i = 0; i < 4; ++i) {
        float4 q = v[i];
        ss += q.x * q.x + q.y * q.y + q.z * q.z + q.w * q.w;
        dst[i * 32 + lane] = make_uint2(pack2(q.x, q.y), pack2(q.z, q.w));
    }
#pragma unroll
    for (int s = 16; s > 0; s >>= 1) ss += __shfl_xor_sync(0xffffffffu, ss, s);
    if (lane == 0) g_invA[r] = 1.0f / fmaxf(sqrtf(ss), EPSF);
}

// -----------------------------------------------------------------------------
// Kernel 1b (centroid): block = speaker j; fp32 sums (L2-warm e) -> g_B [k][n].
// Identical math to the R6-proven version.
// -----------------------------------------------------------------------------
__global__ __launch_bounds__(256) void centroid_kernel(const float* __restrict__ e) {
    int j = blockIdx.x, tid = threadIdx.x;
    const float* base = e + (size_t)j * UUT * DIM;
    float s0 = 0.f, s1 = 0.f;
#pragma unroll 4
    for (int u = 0; u < UUT; ++u) {
        s0 += base[u * DIM + tid];
        s1 += base[u * DIM + tid + 256];
    }
    __shared__ float red[256];
    red[tid] = s0 * s0 + s1 * s1;
    __syncthreads();
    for (int s = 128; s > 0; s >>= 1) {
        if (tid < s) red[tid] += red[tid + s];
        __syncthreads();
    }
    float inv = 1.0f / fmaxf(sqrtf(red[0]), 32.f * EPSF);
    g_B[(size_t)tid * NSPK + j]         = __float2bfloat16(s0 * inv);
    g_B[(size_t)(tid + 256) * NSPK + j] = __float2bfloat16(s1 * inv);
}

// -----------------------------------------------------------------------------
// Kernel 2: bf16 mma.sync GEMM, BM=BN=128, BK=64, THREE-stage cp.async,
// fused softmax-partial epilogue.  (R9 structure, +1 stage)
// smem: 3 stages x (A 16KB + B 16KB) = 96KB + 512B se_sm.
// -----------------------------------------------------------------------------
#define NKT 8            // DIM / 64
#define GEMM_SMEM (98304 + 512)

__global__ __launch_bounds__(256) void gemm_fused_kernel(const float* __restrict__ wp,
                                                         const float* __restrict__ bp) {
    extern __shared__ __align__(1024) char smem[];
    float* se_sm = (float*)(smem + 98304);

    int tid = threadIdx.x;
    int lane = tid & 31, wid = tid >> 5;
    int warp_m = wid & 1, warp_n = wid >> 1;
    int mBase = blockIdx.y * 128, nBase = blockIdx.x * 128;

    uint32_t sbase = smem_u32(smem);

    int arow = tid >> 3, ag = tid & 7;
    int brow = tid >> 4, bg = tid & 15;
    const __nv_bfloat16* aptr = g_A + (size_t)(mBase + arow) * DIM + ag * 8;
    const __nv_bfloat16* bptr = g_B + (size_t)brow * NSPK + nBase + bg * 8;

    float c[4][4][4];
#pragma unroll
    for (int i = 0; i < 4; ++i)
#pragma unroll
        for (int j = 0; j < 4; ++j)
#pragma unroll
            for (int q = 0; q < 4; ++q) c[i][j][q] = 0.f;

#define LOAD_STAGE(s, kt) do {                                                  \
        int k0 = (kt) * 64;                                                     \
        uint32_t sA_ = sbase + (s) * 32768;                                     \
        uint32_t sB_ = sA_ + 16384;                                             \
        CP_ASYNC16(sA_ + aoff2(arow,      ag), aptr + k0);                      \
        CP_ASYNC16(sA_ + aoff2(arow + 32, ag), aptr + k0 + (size_t)32 * DIM);   \
        CP_ASYNC16(sA_ + aoff2(arow + 64, ag), aptr + k0 + (size_t)64 * DIM);   \
        CP_ASYNC16(sA_ + aoff2(arow + 96, ag), aptr + k0 + (size_t)96 * DIM);   \
        CP_ASYNC16(sB_ + boff(brow,      bg), bptr + (size_t)(k0     ) * NSPK); \
        CP_ASYNC16(sB_ + boff(brow + 16, bg), bptr + (size_t)(k0 + 16) * NSPK); \
        CP_ASYNC16(sB_ + boff(brow + 32, bg), bptr + (size_t)(k0 + 32) * NSPK); \
        CP_ASYNC16(sB_ + boff(brow + 48, bg), bptr + (size_t)(k0 + 48) * NSPK); \
        CP_COMMIT();                                                            \
    } while (0)

    LOAD_STAGE(0, 0);
    LOAD_STAGE(1, 1);
    LOAD_STAGE(2, 2);

    int lrow = lane & 15, lsel = lane >> 4;

    for (int kt = 0; kt < NKT; ++kt) {
        if (kt < NKT - 2)       CP_WAIT2();
        else if (kt == NKT - 2) CP_WAIT1();
        else                    CP_WAIT0();
        __syncthreads();

        int s = kt % 3;
        uint32_t sA = sbase + s * 32768;
        uint32_t sB = sA + 16384;

#pragma unroll
        for (int kh = 0; kh < 4; ++kh) {
            uint32_t a[4][4], b[2][4];
#pragma unroll
            for (int mt = 0; mt < 4; ++mt) {
                int row = warp_m * 64 + mt * 16 + lrow;
                LDSM_X4(a[mt], sA + aoff2(row, kh * 2 + lsel));
            }
#pragma unroll
            for (int nt = 0; nt < 2; ++nt) {
                int k = kh * 16 + lrow;
                LDSM_X4T(b[nt], sB + boff(k, warp_n * 4 + nt * 2 + lsel));
            }
#pragma unroll
            for (int mt = 0; mt < 4; ++mt)
#pragma unroll
                for (int n8 = 0; n8 < 4; ++n8) {
                    uint32_t b0 = b[n8 >> 1][(n8 & 1) * 2];
                    uint32_t b1 = b[n8 >> 1][(n8 & 1) * 2 + 1];
                    MMA16816(c[mt][n8], a[mt], b0, b1);
                }
        }
        __syncthreads();
        if (kt + 3 < NKT) LOAD_STAGE((kt + 3) % 3, kt + 3);
    }
#undef LOAD_STAGE

    // ---------------- fused epilogue: partial sum-exp + diag -----------------
    if (tid < 128) se_sm[tid] = 0.f;
    __syncthreads();

    float wv = *wp, bv = *bp;
#pragma unroll
    for (int mt = 0; mt < 4; ++mt) {
#pragma unroll
        for (int sr = 0; sr < 2; ++sr) {
            int row_l = warp_m * 64 + mt * 16 + (lane >> 2) + sr * 8;
            int row_g = mBase + row_l;
            float sc = wv * g_invA[row_g];
            int jdiag = row_g >> 5;
            float part = 0.f;
#pragma unroll
            for (int n8 = 0; n8 < 4; ++n8) {
#pragma unroll
                for (int cc = 0; cc < 2; ++cc) {
                    int col_g = nBase + warp_n * 32 + n8 * 8 + (lane & 3) * 2 + cc;
                    float v = fmaf(c[mt][n8][sr * 2 + cc], sc, bv);
                    part += __expf(v);
                    if (col_g == jdiag) g_vd[row_g] = v;
                }
            }
            part += __shfl_xor_sync(0xffffffffu, part, 1);
            part += __shfl_xor_sync(0xffffffffu, part, 2);
            if ((lane & 3) == 0) atomicAdd(&se_sm[row_l], part);
        }
    }
    __syncthreads();
    if (tid < 128) atomicAdd(&g_se[mBase + tid], se_sm[tid]);
}

// -----------------------------------------------------------------------------
// Kernel 3: loss = mean(log(se) - vd)
// -----------------------------------------------------------------------------
__global__ __launch_bounds__(256) void final_kernel(float* __restrict__ out) {
    int idx = blockIdx.x * 256 + threadIdx.x;
    float v = __logf(g_se[idx]) - g_vd[idx];
#pragma unroll
    for (int s = 16; s > 0; s >>= 1) v += __shfl_xor_sync(0xffffffffu, v, s);
    __shared__ float part[8];
    int wid = threadIdx.x >> 5, lane = threadIdx.x & 31;
    if (lane == 0) part[wid] = v;
    __syncthreads();
    if (threadIdx.x == 0) {
        float s = 0.f;
#pragma unroll
        for (int i = 0; i < 8; ++i) s += part[i];
        atomicAdd(out, s * (1.0f / (float)MROW));
    }
}

// -----------------------------------------------------------------------------
extern "C" void kernel_launch(void* const* d_in, const int* in_sizes, int n_in,
                              void* d_out, int out_size) {
    const float* e = (const float*)d_in[0];  // (512, 32, 512) fp32
    const float* w = (const float*)d_in[1];
    const float* b = (const float*)d_in[2];
    float* out = (float*)d_out;

    cudaFuncSetAttribute(gemm_fused_kernel,
                         cudaFuncAttributeMaxDynamicSharedMemorySize, GEMM_SMEM);

    conv_kernel<<<MROW / 8, 256>>>(e, out);
    centroid_kernel<<<NSPK, 256>>>(e);
    gemm_fused_kernel<<<dim3(NSPK / 128, MROW / 128), 256, GEMM_SMEM>>>(w, b);
    final_kernel<<<MROW / 256, 256>>>(out);
}